// round 4
// baseline (speedup 1.0000x reference)
#include <cuda_runtime.h>

// Problem constants (fixed shapes: B=2048, L=200, D=128, A=64)
#define DD 128
#define AA 64
#define LL 200
#define LP 201                  // padded Kt row stride (odd -> conflict-free)
#define NEGINF (-4294967295.0f) // -2^32 + 1, matches reference

typedef unsigned long long ull;

__device__ __forceinline__ ull pk2(float lo, float hi) {
    ull r; asm("mov.b64 %0,{%1,%2};" : "=l"(r) : "f"(lo), "f"(hi)); return r;
}
__device__ __forceinline__ void upk2(ull v, float& lo, float& hi) {
    asm("mov.b64 {%0,%1},%2;" : "=f"(lo), "=f"(hi) : "l"(v));
}
__device__ __forceinline__ ull ffma2(ull a, ull b, ull c) {
    ull d; asm("fma.rn.f32x2 %0,%1,%2,%3;" : "=l"(d) : "l"(a), "l"(b), "l"(c)); return d;
}

// Shared memory layout (float offsets)
#define OFF_KT   0                      // Kt[128][201] transposed keys
#define OFF_WC   25728                  // Wc[128][64] combined W1 (per-batch)
#define OFF_W2   33920                  // W2[64][64]
#define OFF_H1   38016                  // h1 staging [64][200]
#define OFF_QS   50816                  // q[128]
#define OFF_QC   50944                  // qc[64] (q-part + b1)
#define OFF_QCP  51008                  // qc partials [4][64]
#define OFF_W3   51264                  // W3[64]
#define OFF_B2   51328                  // b2[64]
#define OFF_SC   51392                  // scores/att [256]
#define OFF_RED  51648                  // reduction scratch [32]
#define SMEM_FLOATS 51680
#define SMEM_BYTES  (SMEM_FLOATS * 4)   // 206720 B -> 1 CTA/SM

extern "C" __global__ void __launch_bounds__(256, 1)
din_attention_kernel(const float* __restrict__ query,
                     const float* __restrict__ keys,
                     const int*   __restrict__ klen,
                     const float* __restrict__ W1,
                     const float* __restrict__ b1,
                     const float* __restrict__ a1p,
                     const float* __restrict__ W2,
                     const float* __restrict__ b2,
                     const float* __restrict__ a2p,
                     const float* __restrict__ W3,
                     const float* __restrict__ b3p,
                     float* __restrict__ outp,
                     float* __restrict__ attp)
{
    extern __shared__ float sm[];
    const int t = threadIdx.x;
    const int b = blockIdx.x;

    const float pa1 = a1p[0];
    const float pa2 = a2p[0];
    const float b3v = b3p[0];
    const int   len = klen[b];

    // ---- Setup phase 1: q, W3, b2 into smem ----
    if (t < DD) {
        sm[OFF_QS + t] = query[b * DD + t];
    } else if (t < DD + AA) {
        int a = t - DD; sm[OFF_W3 + a] = W3[a];
    } else {
        int a = t - DD - AA; sm[OFF_B2 + a] = b2[a];
    }
    __syncthreads();

    // ---- Setup phase 2: combined weight Wc, W2, transposed K, qc partials ----
    // Wc[d][a] = (W1b - W1c)[d][a] + q[d] * W1d[d][a]
    for (int i = t; i < DD * AA; i += 256) {
        int d = i >> 6, a = i & 63;
        sm[OFF_WC + i] = W1[(DD + d) * AA + a] - W1[(2 * DD + d) * AA + a]
                       + sm[OFF_QS + d] * W1[(3 * DD + d) * AA + a];
    }
    for (int i = t; i < AA * AA; i += 256) sm[OFF_W2 + i] = W2[i];

    const float* Kb = keys + (size_t)b * LL * DD;
    for (int i = t; i < LL * DD; i += 256) {
        int l = i >> 7, d = i & 127;
        sm[OFF_KT + d * LP + l] = Kb[i];
    }

    // qc partial: qc[a] += q[d] * (W1a + W1c)[d][a]
    {
        int a = t & 63, seg = t >> 6;
        float s = 0.f;
        #pragma unroll 8
        for (int d = seg * 32; d < seg * 32 + 32; d++)
            s += sm[OFF_QS + d] * (W1[d * AA + a] + W1[(2 * DD + d) * AA + a]);
        sm[OFF_QCP + seg * 64 + a] = s;
    }
    __syncthreads();
    if (t < AA)
        sm[OFF_QC + t] = b1[t] + sm[OFF_QCP + t] + sm[OFF_QCP + 64 + t]
                       + sm[OFF_QCP + 128 + t] + sm[OFF_QCP + 192 + t];
    __syncthreads();

    // ---- MLP: thread t handles position l = t ----
    if (t < LL) {
        // h1_pre[a] = qc[a] + sum_d Kt[d][t] * Wc[d][a]   (packed f32x2, 2 MACs/op)
        ull acc[32];
        #pragma unroll
        for (int j = 0; j < 32; j++)
            acc[j] = pk2(sm[OFF_QC + 2 * j], sm[OFF_QC + 2 * j + 1]);

        const float* kt = sm + OFF_KT + t;
        #pragma unroll 2
        for (int d = 0; d < DD; d++) {
            float kv = kt[d * LP];
            ull kv2 = pk2(kv, kv);
            const ulonglong2* wr = (const ulonglong2*)(sm + OFF_WC + d * AA);
            #pragma unroll
            for (int c = 0; c < 16; c++) {
                ulonglong2 w = wr[c];
                acc[2 * c]     = ffma2(kv2, w.x, acc[2 * c]);
                acc[2 * c + 1] = ffma2(kv2, w.y, acc[2 * c + 1]);
            }
        }

        // prelu(a1), stash h1 in smem (own column; no cross-thread use)
        #pragma unroll
        for (int j = 0; j < 32; j++) {
            float lo, hi; upk2(acc[j], lo, hi);
            lo = (lo >= 0.f) ? lo : pa1 * lo;
            hi = (hi >= 0.f) ? hi : pa1 * hi;
            sm[OFF_H1 + (2 * j) * LL + t]     = lo;
            sm[OFF_H1 + (2 * j + 1) * LL + t] = hi;
        }

        // h2_pre[c] = b2[c] + sum_a h1[a] * W2[a][c]
        ull acc2[32];
        #pragma unroll
        for (int j = 0; j < 32; j++)
            acc2[j] = pk2(sm[OFF_B2 + 2 * j], sm[OFF_B2 + 2 * j + 1]);

        #pragma unroll 4
        for (int a = 0; a < AA; a++) {
            float hv = sm[OFF_H1 + a * LL + t];
            ull hv2 = pk2(hv, hv);
            const ulonglong2* wr = (const ulonglong2*)(sm + OFF_W2 + a * AA);
            #pragma unroll
            for (int c = 0; c < 16; c++) {
                ulonglong2 w = wr[c];
                acc2[2 * c]     = ffma2(hv2, w.x, acc2[2 * c]);
                acc2[2 * c + 1] = ffma2(hv2, w.y, acc2[2 * c + 1]);
            }
        }

        // prelu(a2) + score = b3 + h2 . W3, mask by keys_length
        float s = b3v;
        #pragma unroll
        for (int j = 0; j < 32; j++) {
            float lo, hi; upk2(acc2[j], lo, hi);
            lo = (lo >= 0.f) ? lo : pa2 * lo;
            hi = (hi >= 0.f) ? hi : pa2 * hi;
            s += lo * sm[OFF_W3 + 2 * j] + hi * sm[OFF_W3 + 2 * j + 1];
        }
        sm[OFF_SC + t] = (t < len) ? s : NEGINF;
    } else {
        sm[OFF_SC + t] = __int_as_float(0xff800000); // -inf for padding lanes
    }
    __syncthreads();

    // ---- Softmax over L=200 (block reduction, 256 threads) ----
    float v = sm[OFF_SC + t];
    float m = v;
    #pragma unroll
    for (int o = 16; o > 0; o >>= 1) m = fmaxf(m, __shfl_xor_sync(0xffffffffu, m, o));
    if ((t & 31) == 0) sm[OFF_RED + (t >> 5)] = m;
    __syncthreads();
    if (t == 0) {
        float mm = sm[OFF_RED];
        for (int w = 1; w < 8; w++) mm = fmaxf(mm, sm[OFF_RED + w]);
        sm[OFF_RED + 8] = mm;
    }
    __syncthreads();
    float M = sm[OFF_RED + 8];

    float e = (t < LL) ? __expf(v - M) : 0.f;
    float ssum = e;
    #pragma unroll
    for (int o = 16; o > 0; o >>= 1) ssum += __shfl_xor_sync(0xffffffffu, ssum, o);
    if ((t & 31) == 0) sm[OFF_RED + 16 + (t >> 5)] = ssum;
    __syncthreads();
    if (t == 0) {
        float s2 = 0.f;
        for (int w = 0; w < 8; w++) s2 += sm[OFF_RED + 16 + w];
        sm[OFF_RED + 24] = s2;
    }
    __syncthreads();
    float S = sm[OFF_RED + 24];

    if (t < LL) {
        float at = e / S;
        sm[OFF_SC + t] = at;
        attp[(size_t)b * LL + t] = at;
    }
    __syncthreads();

    // ---- out[b][d] = sum_l att[l] * K[l][d]  (thread = d, att broadcast) ----
    if (t < DD) {
        const float* kr = sm + OFF_KT + t * LP;
        float s0 = 0.f, s1 = 0.f, s2 = 0.f, s3 = 0.f;
        #pragma unroll 2
        for (int l = 0; l < LL; l += 4) {
            s0 += sm[OFF_SC + l]     * kr[l];
            s1 += sm[OFF_SC + l + 1] * kr[l + 1];
            s2 += sm[OFF_SC + l + 2] * kr[l + 2];
            s3 += sm[OFF_SC + l + 3] * kr[l + 3];
        }
        outp[(size_t)b * DD + t] = (s0 + s1) + (s2 + s3);
    }
}

extern "C" void kernel_launch(void* const* d_in, const int* in_sizes, int n_in,
                              void* d_out, int out_size) {
    const float* query = (const float*)d_in[0];
    const float* keys  = (const float*)d_in[1];
    const int*   klen  = (const int*)  d_in[2];
    const float* W1    = (const float*)d_in[3];
    const float* b1    = (const float*)d_in[4];
    const float* a1    = (const float*)d_in[5];
    const float* W2    = (const float*)d_in[6];
    const float* b2    = (const float*)d_in[7];
    const float* a2    = (const float*)d_in[8];
    const float* W3    = (const float*)d_in[9];
    const float* b3    = (const float*)d_in[10];

    int Bn = in_sizes[0] / DD;  // 2048
    float* outp = (float*)d_out;               // (B, D)
    float* attp = outp + (size_t)Bn * DD;      // (B, L)

    cudaFuncSetAttribute(din_attention_kernel,
                         cudaFuncAttributeMaxDynamicSharedMemorySize, SMEM_BYTES);
    din_attention_kernel<<<Bn, 256, SMEM_BYTES>>>(
        query, keys, klen, W1, b1, a1, W2, b2, a2, W3, b3, outp, attp);
}

// round 5
// speedup vs baseline: 1.0329x; 1.0329x over previous
#include <cuda_runtime.h>

// Problem constants (fixed shapes: B=2048, L=200, D=128, A=64)
#define DD 128
#define AA 64
#define LL 200
#define LP 201                  // padded Kt row stride (odd -> conflict-free)
#define NEGINF (-4294967295.0f) // -2^32 + 1, matches reference

typedef unsigned long long ull;

__device__ __forceinline__ ull pk2(float lo, float hi) {
    ull r; asm("mov.b64 %0,{%1,%2};" : "=l"(r) : "f"(lo), "f"(hi)); return r;
}
__device__ __forceinline__ void upk2(ull v, float& lo, float& hi) {
    asm("mov.b64 {%0,%1},%2;" : "=f"(lo), "=f"(hi) : "l"(v));
}
__device__ __forceinline__ ull ffma2(ull a, ull b, ull c) {
    ull d; asm("fma.rn.f32x2 %0,%1,%2,%3;" : "=l"(d) : "l"(a), "l"(b), "l"(c)); return d;
}

// Shared memory layout (float offsets)
#define OFF_KT   0                      // Kt[128][201] transposed keys
#define OFF_WC   25728                  // Wc[128][64]; reused as GEMM2 partial [32][200]
#define OFF_W2   33920                  // W2[64][64]
#define OFF_H1   38016                  // GEMM1 partial / h1 [64][200]
#define OFF_QS   50816                  // q[128]
#define OFF_QC   50944                  // qc[64]
#define OFF_QCP  51008                  // qc partials [8][64] / out partials [4][128]
#define OFF_W3   51520                  // W3[64]
#define OFF_B2   51584                  // b2[64]
#define OFF_SC   51648                  // scores/att [256]
#define OFF_RED  51904                  // reduction scratch [32]
#define SMEM_FLOATS 51968
#define SMEM_BYTES  (SMEM_FLOATS * 4)   // 207872 B -> 1 CTA/SM

extern "C" __global__ void __launch_bounds__(512, 1)
din_attention_kernel(const float* __restrict__ query,
                     const float* __restrict__ keys,
                     const int*   __restrict__ klen,
                     const float* __restrict__ W1,
                     const float* __restrict__ b1,
                     const float* __restrict__ a1p,
                     const float* __restrict__ W2,
                     const float* __restrict__ b2,
                     const float* __restrict__ a2p,
                     const float* __restrict__ W3,
                     const float* __restrict__ b3p,
                     float* __restrict__ outp,
                     float* __restrict__ attp)
{
    extern __shared__ float sm[];
    const int t    = threadIdx.x;
    const int b    = blockIdx.x;
    const int l    = t & 255;       // position slot (0..255, active if < 200)
    const int half = t >> 8;        // 0 or 1

    const float pa1 = a1p[0];
    const float pa2 = a2p[0];
    const float b3v = b3p[0];
    const int   len = klen[b];

    // ---- Setup phase 1: q, W3, b2 into smem ----
    if (t < DD) {
        sm[OFF_QS + t] = query[b * DD + t];
    } else if (t < DD + AA) {
        sm[OFF_W3 + (t - DD)] = W3[t - DD];
    } else if (t < DD + 2 * AA) {
        sm[OFF_B2 + (t - DD - AA)] = b2[t - DD - AA];
    }
    __syncthreads();

    // ---- Setup phase 2: Wc, W2, transposed K, qc partials (512 threads) ----
    // Wc[d][a] = (W1b - W1c)[d][a] + q[d] * W1d[d][a]
    for (int i = t; i < DD * AA; i += 512) {
        int d = i >> 6;
        sm[OFF_WC + i] = W1[(DD + d) * AA + (i & 63)] - W1[(2 * DD + d) * AA + (i & 63)]
                       + sm[OFF_QS + d] * W1[(3 * DD + d) * AA + (i & 63)];
    }
    for (int i = t; i < AA * AA; i += 512) sm[OFF_W2 + i] = W2[i];

    const float* Kb = keys + (size_t)b * LL * DD;
    for (int i = t; i < LL * DD; i += 512) {
        int kl = i >> 7, d = i & 127;
        sm[OFF_KT + d * LP + kl] = Kb[i];
    }

    // qc partial: 8 segments of 16 d each
    {
        int a = t & 63, seg = t >> 6;
        float s = 0.f;
        #pragma unroll
        for (int d = seg * 16; d < seg * 16 + 16; d++)
            s += sm[OFF_QS + d] * (W1[d * AA + a] + W1[(2 * DD + d) * AA + a]);
        sm[OFF_QCP + seg * 64 + a] = s;
    }
    __syncthreads();
    if (t < AA) {
        float s = b1[t];
        #pragma unroll
        for (int g = 0; g < 8; g++) s += sm[OFF_QCP + g * 64 + t];
        sm[OFF_QC + t] = s;
    }
    __syncthreads();

    // ==== GEMM1, d-split: half h covers d in [h*64, h*64+64) ====
    ull acc[32];
    if (l < LL) {
        if (half == 0) {
            const ull* qc2 = (const ull*)(sm + OFF_QC);
            #pragma unroll
            for (int j = 0; j < 32; j++) acc[j] = qc2[j];
        } else {
            #pragma unroll
            for (int j = 0; j < 32; j++) acc[j] = 0ULL;
        }
        const float* kt = sm + OFF_KT + l + (half << 6) * LP;
        const int dbase = half << 6;
        #pragma unroll 2
        for (int d = 0; d < 64; d++) {
            float kv = kt[d * LP];
            ull kv2 = pk2(kv, kv);
            const ulonglong2* wr = (const ulonglong2*)(sm + OFF_WC + (dbase + d) * AA);
            #pragma unroll
            for (int c = 0; c < 16; c++) {
                ulonglong2 w = wr[c];
                acc[2 * c]     = ffma2(kv2, w.x, acc[2 * c]);
                acc[2 * c + 1] = ffma2(kv2, w.y, acc[2 * c + 1]);
            }
        }
        if (half == 1) {  // stash partial [a][l]
            #pragma unroll
            for (int j = 0; j < 32; j++) {
                float lo, hi; upk2(acc[j], lo, hi);
                sm[OFF_H1 + (2 * j) * LL + l]     = lo;
                sm[OFF_H1 + (2 * j + 1) * LL + l] = hi;
            }
        }
    }
    __syncthreads();
    if (l < LL && half == 0) {  // reduce + prelu(a1) -> h1 in place
        #pragma unroll
        for (int j = 0; j < 32; j++) {
            float lo, hi; upk2(acc[j], lo, hi);
            lo += sm[OFF_H1 + (2 * j) * LL + l];
            hi += sm[OFF_H1 + (2 * j + 1) * LL + l];
            lo = (lo >= 0.f) ? lo : pa1 * lo;
            hi = (hi >= 0.f) ? hi : pa1 * hi;
            sm[OFF_H1 + (2 * j) * LL + l]     = lo;
            sm[OFF_H1 + (2 * j + 1) * LL + l] = hi;
        }
    }
    __syncthreads();

    // ==== GEMM2, a-split: half h covers a in [h*32, h*32+32), all 64 c ====
    ull acc2[32];
    if (l < LL) {
        if (half == 0) {
            const ull* b22 = (const ull*)(sm + OFF_B2);
            #pragma unroll
            for (int j = 0; j < 32; j++) acc2[j] = b22[j];
        } else {
            #pragma unroll
            for (int j = 0; j < 32; j++) acc2[j] = 0ULL;
        }
        const int abase = half << 5;
        #pragma unroll 2
        for (int a = 0; a < 32; a++) {
            float hv = sm[OFF_H1 + (abase + a) * LL + l];
            ull hv2 = pk2(hv, hv);
            const ulonglong2* wr = (const ulonglong2*)(sm + OFF_W2 + (abase + a) * AA);
            #pragma unroll
            for (int c = 0; c < 16; c++) {
                ulonglong2 w = wr[c];
                acc2[2 * c]     = ffma2(hv2, w.x, acc2[2 * c]);
                acc2[2 * c + 1] = ffma2(hv2, w.y, acc2[2 * c + 1]);
            }
        }
    }
    __syncthreads();   // all W2/h1 reads done; Wc area now reusable

    // Reduce acc2 halves in two 32-c chunks via the dead Wc area, fold PReLU+W3.
    float s = b3v;
    #pragma unroll
    for (int chunk = 0; chunk < 2; chunk++) {
        if (l < LL && half == 1) {
            #pragma unroll
            for (int j = 0; j < 16; j++) {
                float lo, hi; upk2(acc2[chunk * 16 + j], lo, hi);
                sm[OFF_WC + (2 * j) * LL + l]     = lo;
                sm[OFF_WC + (2 * j + 1) * LL + l] = hi;
            }
        }
        __syncthreads();
        if (l < LL && half == 0) {
            #pragma unroll
            for (int j = 0; j < 16; j++) {
                float lo, hi; upk2(acc2[chunk * 16 + j], lo, hi);
                lo += sm[OFF_WC + (2 * j) * LL + l];
                hi += sm[OFF_WC + (2 * j + 1) * LL + l];
                lo = (lo >= 0.f) ? lo : pa2 * lo;
                hi = (hi >= 0.f) ? hi : pa2 * hi;
                s += lo * sm[OFF_W3 + chunk * 32 + 2 * j]
                   + hi * sm[OFF_W3 + chunk * 32 + 2 * j + 1];
            }
        }
        __syncthreads();
    }

    // Scores into SC (half 0 owns slots 0..255)
    if (half == 0) {
        if (l < LL) sm[OFF_SC + l] = (l < len) ? s : NEGINF;
        else        sm[OFF_SC + l] = __int_as_float(0xff800000); // -inf pad
    }
    __syncthreads();

    // ---- Softmax over L=200 (warps 0..7 reduce; all threads hit barriers) ----
    float v = 0.f, e = 0.f;
    if (t < 256) {
        v = sm[OFF_SC + t];
        float m = v;
        #pragma unroll
        for (int o = 16; o > 0; o >>= 1) m = fmaxf(m, __shfl_xor_sync(0xffffffffu, m, o));
        if ((t & 31) == 0) sm[OFF_RED + (t >> 5)] = m;
    }
    __syncthreads();
    if (t == 0) {
        float mm = sm[OFF_RED];
        for (int w = 1; w < 8; w++) mm = fmaxf(mm, sm[OFF_RED + w]);
        sm[OFF_RED + 8] = mm;
    }
    __syncthreads();
    if (t < 256) {
        float M = sm[OFF_RED + 8];
        e = (t < LL) ? __expf(v - M) : 0.f;
        float ssum = e;
        #pragma unroll
        for (int o = 16; o > 0; o >>= 1) ssum += __shfl_xor_sync(0xffffffffu, ssum, o);
        if ((t & 31) == 0) sm[OFF_RED + 16 + (t >> 5)] = ssum;
    }
    __syncthreads();
    if (t == 0) {
        float s2 = 0.f;
        for (int w = 0; w < 8; w++) s2 += sm[OFF_RED + 16 + w];
        sm[OFF_RED + 24] = s2;
    }
    __syncthreads();
    if (t < LL) {
        float at = e / sm[OFF_RED + 24];
        sm[OFF_SC + t] = at;
        attp[(size_t)b * LL + t] = at;
    }
    __syncthreads();

    // ---- out[b][d] = sum_l att[l] * K[l][d], 4-way l-split over 512 threads ----
    {
        int d = t & 127, seg = t >> 7;           // seg 0..3, 50 l each
        const float* kr = sm + OFF_KT + d * LP + seg * 50;
        const float* at = sm + OFF_SC + seg * 50;
        float s0 = 0.f, s1 = 0.f;
        #pragma unroll 5
        for (int ll2 = 0; ll2 < 50; ll2 += 2) {
            s0 += at[ll2]     * kr[ll2];
            s1 += at[ll2 + 1] * kr[ll2 + 1];
        }
        sm[OFF_QCP + seg * 128 + d] = s0 + s1;
    }
    __syncthreads();
    if (t < DD) {
        outp[(size_t)b * DD + t] = (sm[OFF_QCP + t] + sm[OFF_QCP + 128 + t])
                                 + (sm[OFF_QCP + 256 + t] + sm[OFF_QCP + 384 + t]);
    }
}

extern "C" void kernel_launch(void* const* d_in, const int* in_sizes, int n_in,
                              void* d_out, int out_size) {
    const float* query = (const float*)d_in[0];
    const float* keys  = (const float*)d_in[1];
    const int*   klen  = (const int*)  d_in[2];
    const float* W1    = (const float*)d_in[3];
    const float* b1    = (const float*)d_in[4];
    const float* a1    = (const float*)d_in[5];
    const float* W2    = (const float*)d_in[6];
    const float* b2    = (const float*)d_in[7];
    const float* a2    = (const float*)d_in[8];
    const float* W3    = (const float*)d_in[9];
    const float* b3    = (const float*)d_in[10];

    int Bn = in_sizes[0] / DD;  // 2048
    float* outp = (float*)d_out;               // (B, D)
    float* attp = outp + (size_t)Bn * DD;      // (B, L)

    cudaFuncSetAttribute(din_attention_kernel,
                         cudaFuncAttributeMaxDynamicSharedMemorySize, SMEM_BYTES);
    din_attention_kernel<<<Bn, 512, SMEM_BYTES>>>(
        query, keys, klen, W1, b1, a1, W2, b2, a2, W3, b3, outp, attp);
}

// round 6
// speedup vs baseline: 1.1196x; 1.0840x over previous
#include <cuda_runtime.h>

// Problem constants (fixed shapes: B=2048, L=200, D=128, A=64)
#define DD 128
#define AA 64
#define LL 200
#define LP 201                  // padded Kt row stride (odd -> conflict-free)
#define NEGINF (-4294967295.0f) // -2^32 + 1, matches reference

typedef unsigned long long ull;

__device__ __forceinline__ ull pk2(float lo, float hi) {
    ull r; asm("mov.b64 %0,{%1,%2};" : "=l"(r) : "f"(lo), "f"(hi)); return r;
}
__device__ __forceinline__ void upk2(ull v, float& lo, float& hi) {
    asm("mov.b64 {%0,%1},%2;" : "=f"(lo), "=f"(hi) : "l"(v));
}
__device__ __forceinline__ ull ffma2(ull a, ull b, ull c) {
    ull d; asm("fma.rn.f32x2 %0,%1,%2,%3;" : "=l"(d) : "l"(a), "l"(b), "l"(c)); return d;
}

// Shared memory layout (float offsets)
#define OFF_KT   0                      // Kt[128][201] transposed keys
#define OFF_WC   25728                  // Wc[128][64] combined W1 (per-batch)
#define OFF_W2   33920                  // W2[64][64]
#define OFF_H1   38016                  // h1 [64][200]
#define OFF_QS   50816                  // q[128]
#define OFF_QC   50944                  // qc[64]
#define OFF_QCP  51008                  // qc partials [8][64] / out partials [4][128]
#define OFF_W3   51520                  // W3[64]
#define OFF_B2   51584                  // b2[64]
#define OFF_SC   51648                  // scores/att [256]
#define OFF_SP   51904                  // score partials [256]
#define OFF_RED  52160                  // reduction scratch [32]
#define SMEM_FLOATS 52192
#define SMEM_BYTES  (SMEM_FLOATS * 4)   // 208768 B -> 1 CTA/SM

extern "C" __global__ void __launch_bounds__(512, 1)
din_attention_kernel(const float* __restrict__ query,
                     const float* __restrict__ keys,
                     const int*   __restrict__ klen,
                     const float* __restrict__ W1,
                     const float* __restrict__ b1,
                     const float* __restrict__ a1p,
                     const float* __restrict__ W2,
                     const float* __restrict__ b2,
                     const float* __restrict__ a2p,
                     const float* __restrict__ W3,
                     const float* __restrict__ b3p,
                     float* __restrict__ outp,
                     float* __restrict__ attp)
{
    extern __shared__ float sm[];
    const int t    = threadIdx.x;
    const int b    = blockIdx.x;
    const int l    = t & 255;       // position slot (0..255, active if < 200)
    const int half = t >> 8;        // output-column half: c in [half*32, half*32+32)

    const float pa1 = a1p[0];
    const float pa2 = a2p[0];
    const float b3v = b3p[0];
    const int   len = klen[b];

    // ---- Setup phase 1: q, W3, b2 into smem ----
    if (t < DD) {
        sm[OFF_QS + t] = query[b * DD + t];
    } else if (t < DD + AA) {
        sm[OFF_W3 + (t - DD)] = W3[t - DD];
    } else if (t < DD + 2 * AA) {
        sm[OFF_B2 + (t - DD - AA)] = b2[t - DD - AA];
    }
    __syncthreads();

    // ---- Setup phase 2: Wc, W2, transposed K, qc partials (512 threads) ----
    // Wc[d][a] = (W1b - W1c)[d][a] + q[d] * W1d[d][a]
    for (int i = t; i < DD * AA; i += 512) {
        int d = i >> 6;
        sm[OFF_WC + i] = W1[(DD + d) * AA + (i & 63)] - W1[(2 * DD + d) * AA + (i & 63)]
                       + sm[OFF_QS + d] * W1[(3 * DD + d) * AA + (i & 63)];
    }
    for (int i = t; i < AA * AA; i += 512) sm[OFF_W2 + i] = W2[i];

    const float* Kb = keys + (size_t)b * LL * DD;
    for (int i = t; i < LL * DD; i += 512) {
        int kl = i >> 7, d = i & 127;
        sm[OFF_KT + d * LP + kl] = Kb[i];
    }

    // qc partial: 8 segments of 16 d each; qc[a] = b1[a] + sum_d q[d]*(W1a+W1c)[d][a]
    {
        int a = t & 63, seg = t >> 6;
        float s = 0.f;
        #pragma unroll
        for (int d = seg * 16; d < seg * 16 + 16; d++)
            s += sm[OFF_QS + d] * (W1[d * AA + a] + W1[(2 * DD + d) * AA + a]);
        sm[OFF_QCP + seg * 64 + a] = s;
    }
    __syncthreads();
    if (t < AA) {
        float s = b1[t];
        #pragma unroll
        for (int g = 0; g < 8; g++) s += sm[OFF_QCP + g * 64 + t];
        sm[OFF_QC + t] = s;
    }
    __syncthreads();

    // ==== GEMM1, c-split: thread (l, half) computes h1[c] for its 32 c's,
    //      full d-reduction (no cross-thread partials, 16-ull accumulator) ====
    const int cbase = half << 5;
    if (l < LL) {
        ull acc[16];
        const ull* qc2 = (const ull*)(sm + OFF_QC + cbase);
        #pragma unroll
        for (int j = 0; j < 16; j++) acc[j] = qc2[j];

        const float* kt = sm + OFF_KT + l;
        const ulonglong2* wr = (const ulonglong2*)(sm + OFF_WC + cbase);
        #pragma unroll 4
        for (int d = 0; d < DD; d++) {
            float kv = kt[d * LP];
            ull kv2 = pk2(kv, kv);
            const ulonglong2* w = wr + d * (AA / 4);
            #pragma unroll
            for (int c8 = 0; c8 < 8; c8++) {
                ulonglong2 wv = w[c8];
                acc[2 * c8]     = ffma2(kv2, wv.x, acc[2 * c8]);
                acc[2 * c8 + 1] = ffma2(kv2, wv.y, acc[2 * c8 + 1]);
            }
        }
        // prelu(a1) -> h1[c][l]
        #pragma unroll
        for (int j = 0; j < 16; j++) {
            float lo, hi; upk2(acc[j], lo, hi);
            lo = (lo >= 0.f) ? lo : pa1 * lo;
            hi = (hi >= 0.f) ? hi : pa1 * hi;
            sm[OFF_H1 + (cbase + 2 * j) * LL + l]     = lo;
            sm[OFF_H1 + (cbase + 2 * j + 1) * LL + l] = hi;
        }
    }
    __syncthreads();

    // ==== GEMM2, c-split: thread (l, half) computes h2[c] for its 32 c's,
    //      full a-reduction ====
    float s = (half == 0) ? b3v : 0.f;
    if (l < LL) {
        ull acc2[16];
        const ull* b22 = (const ull*)(sm + OFF_B2 + cbase);
        #pragma unroll
        for (int j = 0; j < 16; j++) acc2[j] = b22[j];

        const ulonglong2* wr2 = (const ulonglong2*)(sm + OFF_W2 + cbase);
        #pragma unroll 4
        for (int a = 0; a < AA; a++) {
            float hv = sm[OFF_H1 + a * LL + l];
            ull hv2 = pk2(hv, hv);
            const ulonglong2* w = wr2 + a * (AA / 4);
            #pragma unroll
            for (int c8 = 0; c8 < 8; c8++) {
                ulonglong2 wv = w[c8];
                acc2[2 * c8]     = ffma2(hv2, wv.x, acc2[2 * c8]);
                acc2[2 * c8 + 1] = ffma2(hv2, wv.y, acc2[2 * c8 + 1]);
            }
        }
        // prelu(a2) + partial score over this half's 32 c's
        #pragma unroll
        for (int j = 0; j < 16; j++) {
            float lo, hi; upk2(acc2[j], lo, hi);
            lo = (lo >= 0.f) ? lo : pa2 * lo;
            hi = (hi >= 0.f) ? hi : pa2 * hi;
            s += lo * sm[OFF_W3 + cbase + 2 * j] + hi * sm[OFF_W3 + cbase + 2 * j + 1];
        }
        if (half == 1) sm[OFF_SP + l] = s;
    }
    __syncthreads();

    // Combine score halves, mask by keys_length
    if (half == 0) {
        if (l < LL) sm[OFF_SC + l] = (l < len) ? (s + sm[OFF_SP + l]) : NEGINF;
        else        sm[OFF_SC + l] = __int_as_float(0xff800000); // -inf pad
    }
    __syncthreads();

    // ---- Softmax over L=200 (warps 0..7 reduce; all threads hit barriers) ----
    float v = 0.f, e = 0.f;
    if (t < 256) {
        v = sm[OFF_SC + t];
        float m = v;
        #pragma unroll
        for (int o = 16; o > 0; o >>= 1) m = fmaxf(m, __shfl_xor_sync(0xffffffffu, m, o));
        if ((t & 31) == 0) sm[OFF_RED + (t >> 5)] = m;
    }
    __syncthreads();
    if (t == 0) {
        float mm = sm[OFF_RED];
        for (int w = 1; w < 8; w++) mm = fmaxf(mm, sm[OFF_RED + w]);
        sm[OFF_RED + 8] = mm;
    }
    __syncthreads();
    if (t < 256) {
        float M = sm[OFF_RED + 8];
        e = (t < LL) ? __expf(v - M) : 0.f;
        float ssum = e;
        #pragma unroll
        for (int o = 16; o > 0; o >>= 1) ssum += __shfl_xor_sync(0xffffffffu, ssum, o);
        if ((t & 31) == 0) sm[OFF_RED + 16 + (t >> 5)] = ssum;
    }
    __syncthreads();
    if (t == 0) {
        float s2 = 0.f;
        for (int w = 0; w < 8; w++) s2 += sm[OFF_RED + 16 + w];
        sm[OFF_RED + 24] = s2;
    }
    __syncthreads();
    if (t < LL) {
        float at = e / sm[OFF_RED + 24];
        sm[OFF_SC + t] = at;
        attp[(size_t)b * LL + t] = at;
    }
    __syncthreads();

    // ---- out[b][d] = sum_l att[l] * K[l][d], 4-way l-split over 512 threads ----
    {
        int d = t & 127, seg = t >> 7;           // seg 0..3, 50 l each
        const float* kr = sm + OFF_KT + d * LP + seg * 50;
        const float* at = sm + OFF_SC + seg * 50;
        float s0 = 0.f, s1 = 0.f;
        #pragma unroll 5
        for (int ll2 = 0; ll2 < 50; ll2 += 2) {
            s0 += at[ll2]     * kr[ll2];
            s1 += at[ll2 + 1] * kr[ll2 + 1];
        }
        sm[OFF_QCP + seg * 128 + d] = s0 + s1;
    }
    __syncthreads();
    if (t < DD) {
        outp[(size_t)b * DD + t] = (sm[OFF_QCP + t] + sm[OFF_QCP + 128 + t])
                                 + (sm[OFF_QCP + 256 + t] + sm[OFF_QCP + 384 + t]);
    }
}

extern "C" void kernel_launch(void* const* d_in, const int* in_sizes, int n_in,
                              void* d_out, int out_size) {
    const float* query = (const float*)d_in[0];
    const float* keys  = (const float*)d_in[1];
    const int*   klen  = (const int*)  d_in[2];
    const float* W1    = (const float*)d_in[3];
    const float* b1    = (const float*)d_in[4];
    const float* a1    = (const float*)d_in[5];
    const float* W2    = (const float*)d_in[6];
    const float* b2    = (const float*)d_in[7];
    const float* a2    = (const float*)d_in[8];
    const float* W3    = (const float*)d_in[9];
    const float* b3    = (const float*)d_in[10];

    int Bn = in_sizes[0] / DD;  // 2048
    float* outp = (float*)d_out;               // (B, D)
    float* attp = outp + (size_t)Bn * DD;      // (B, L)

    cudaFuncSetAttribute(din_attention_kernel,
                         cudaFuncAttributeMaxDynamicSharedMemorySize, SMEM_BYTES);
    din_attention_kernel<<<Bn, 512, SMEM_BYTES>>>(
        query, keys, klen, W1, b1, a1, W2, b2, a2, W3, b3, outp, attp);
}

// round 8
// speedup vs baseline: 1.1445x; 1.0222x over previous
#include <cuda_runtime.h>
#include <cstdint>

// Fixed shapes: B=2048, L=200, D=128, A=64
#define DD 128
#define AA 64
#define LL 200
#define NEGINF (-4294967295.0f)
#define FNEGINF __int_as_float(0xff800000)

typedef unsigned long long ull;

__device__ __forceinline__ ull pk2(float lo, float hi) {
    ull r; asm("mov.b64 %0,{%1,%2};" : "=l"(r) : "f"(lo), "f"(hi)); return r;
}
__device__ __forceinline__ void upk2(ull v, float& lo, float& hi) {
    asm("mov.b64 {%0,%1},%2;" : "=f"(lo), "=f"(hi) : "l"(v));
}
__device__ __forceinline__ ull ffma2(ull a, ull b, ull c) {
    ull d; asm("fma.rn.f32x2 %0,%1,%2,%3;" : "=l"(d) : "l"(a), "l"(b), "l"(c)); return d;
}

// ---- smem layout (float offsets) ----
#define F_KS   0          // K natural [200][128]           25600
#define F_WC   25600      // Wc [128][64]                    8192
#define F_W2   33792      // W2 [64][64]                     4096
#define F_H1T  37888      // h1 transposed [64][200]        12800
#define F_QS   50688      // q[128]
#define F_QC   50816      // qc[64]  (8B aligned)
#define F_B2   50880      // b2[64]
#define F_W3   50944      // W3[64]
#define F_QCP  51008      // qc partials [8][64]
#define F_SC   51520      // scores/att [256]
#define F_RED  51776      // softmax scratch [32]
#define F_OUT  51808      // out partials [4][128]
#define SMEM_FLOATS 52320
#define SMEM_BYTES  (SMEM_FLOATS * 4)   // 209280 B -> 1 CTA/SM

extern "C" __global__ void __launch_bounds__(512)
din_attention_rt(const float* __restrict__ query,
                 const float* __restrict__ keys,
                 const int*   __restrict__ klen,
                 const float* __restrict__ W1,
                 const float* __restrict__ b1,
                 const float* __restrict__ a1p,
                 const float* __restrict__ W2,
                 const float* __restrict__ b2,
                 const float* __restrict__ a2p,
                 const float* __restrict__ W3,
                 const float* __restrict__ b3p,
                 float* __restrict__ outp,
                 float* __restrict__ attp)
{
    extern __shared__ float sm[];
    const int t    = threadIdx.x;
    const int b    = blockIdx.x;
    const int lg   = t >> 3;        // 0..63 ; active if < 50
    const int cg   = t & 7;         // 0..7
    const int l0   = lg * 4;
    const int c0   = cg * 8;
    const int lane = t & 31;
    const int w    = t >> 5;

    const float pa1 = a1p[0], pa2 = a2p[0], b3v = b3p[0];
    const int   len = klen[b];

    // ---- Setup 1: q, W3, b2 ----
    if (t < DD) sm[F_QS + t] = query[b * DD + t];
    else if (t < DD + AA) sm[F_W3 + (t - DD)] = W3[t - DD];
    else if (t < DD + 2 * AA) sm[F_B2 + (t - DD - AA)] = b2[t - DD - AA];
    __syncthreads();

    // ---- Setup 2: Wc, W2, K copy, qc partials ----
    // Wc[d][c] = (W1b - W1c)[d][c] + q[d]*W1d[d][c]
    for (int i = t; i < DD * AA; i += 512) {
        int d = i >> 6, c = i & 63;
        sm[F_WC + i] = W1[(DD + d) * AA + c] - W1[(2 * DD + d) * AA + c]
                     + sm[F_QS + d] * W1[(3 * DD + d) * AA + c];
    }
    for (int i = t; i < AA * AA; i += 512) sm[F_W2 + i] = W2[i];

    {   // K natural copy, vectorized
        const float4* K4 = (const float4*)(keys + (size_t)b * LL * DD);
        float4* S4 = (float4*)(sm + F_KS);
        for (int i = t; i < LL * DD / 4; i += 512) S4[i] = K4[i];
    }

    {   // qc[a] = b1[a] + sum_d q[d]*(W1a+W1c)[d][a]
        int a = t & 63, seg = t >> 6;
        float s = 0.f;
        #pragma unroll
        for (int d = seg * 16; d < seg * 16 + 16; d++)
            s += sm[F_QS + d] * (W1[d * AA + a] + W1[(2 * DD + d) * AA + a]);
        sm[F_QCP + seg * 64 + a] = s;
    }
    __syncthreads();
    if (t < AA) {
        float s = b1[t];
        #pragma unroll
        for (int g = 0; g < 8; g++) s += sm[F_QCP + g * 64 + t];
        sm[F_QC + t] = s;
    }
    __syncthreads();

    // ==== GEMM1: h1[l][c] = prelu(qc[c] + sum_d K[l][d]*Wc[d][c]), tile 4l x 8c ====
    if (lg < 50) {
        ull acc[4][4];
        {
            const ull* qc2 = (const ull*)(sm + F_QC + c0);
            ull q0 = qc2[0], q1 = qc2[1], q2 = qc2[2], q3 = qc2[3];
            #pragma unroll
            for (int li = 0; li < 4; li++) {
                acc[li][0] = q0; acc[li][1] = q1; acc[li][2] = q2; acc[li][3] = q3;
            }
        }
        #pragma unroll 1
        for (int d = 0; d < DD; d += 4) {
            float kvf[4][4];
            #pragma unroll
            for (int li = 0; li < 4; li++) {
                float4 kv = *(const float4*)(sm + F_KS + (l0 + li) * DD + d);
                kvf[li][0] = kv.x; kvf[li][1] = kv.y; kvf[li][2] = kv.z; kvf[li][3] = kv.w;
            }
            #pragma unroll
            for (int dd = 0; dd < 4; dd++) {
                const ulonglong2* wr = (const ulonglong2*)(sm + F_WC + (d + dd) * AA + c0);
                ulonglong2 wa = wr[0], wb = wr[1];
                #pragma unroll
                for (int li = 0; li < 4; li++) {
                    ull k2 = pk2(kvf[li][dd], kvf[li][dd]);
                    acc[li][0] = ffma2(k2, wa.x, acc[li][0]);
                    acc[li][1] = ffma2(k2, wa.y, acc[li][1]);
                    acc[li][2] = ffma2(k2, wb.x, acc[li][2]);
                    acc[li][3] = ffma2(k2, wb.y, acc[li][3]);
                }
            }
        }
        // prelu(a1) -> h1t[c][l0..3] as float4 along l
        float hv[4][8];
        #pragma unroll
        for (int li = 0; li < 4; li++)
            #pragma unroll
            for (int j = 0; j < 4; j++) {
                float lo, hi; upk2(acc[li][j], lo, hi);
                hv[li][2 * j]     = (lo >= 0.f) ? lo : pa1 * lo;
                hv[li][2 * j + 1] = (hi >= 0.f) ? hi : pa1 * hi;
            }
        #pragma unroll
        for (int j = 0; j < 8; j++) {
            float4 v = make_float4(hv[0][j], hv[1][j], hv[2][j], hv[3][j]);
            *(float4*)(sm + F_H1T + (c0 + j) * LL + l0) = v;
        }
    }
    __syncthreads();

    // ==== GEMM2: h2[l][c] = b2[c] + sum_a h1[l][a]*W2[a][c], tile 4l x 8c ====
    float s0 = 0.f, s1 = 0.f, s2 = 0.f, s3 = 0.f;   // per-li score partials
    if (lg < 50) {
        ull acc[4][4];
        {
            const ull* b22 = (const ull*)(sm + F_B2 + c0);
            ull q0 = b22[0], q1 = b22[1], q2 = b22[2], q3 = b22[3];
            #pragma unroll
            for (int li = 0; li < 4; li++) {
                acc[li][0] = q0; acc[li][1] = q1; acc[li][2] = q2; acc[li][3] = q3;
            }
        }
        #pragma unroll 1
        for (int a = 0; a < AA; a += 4) {
            float hq[4][4];   // [aa][li]
            #pragma unroll
            for (int aa = 0; aa < 4; aa++) {
                float4 h4 = *(const float4*)(sm + F_H1T + (a + aa) * LL + l0);
                hq[aa][0] = h4.x; hq[aa][1] = h4.y; hq[aa][2] = h4.z; hq[aa][3] = h4.w;
            }
            #pragma unroll
            for (int aa = 0; aa < 4; aa++) {
                const ulonglong2* wr = (const ulonglong2*)(sm + F_W2 + (a + aa) * AA + c0);
                ulonglong2 wa = wr[0], wb = wr[1];
                #pragma unroll
                for (int li = 0; li < 4; li++) {
                    ull k2 = pk2(hq[aa][li], hq[aa][li]);
                    acc[li][0] = ffma2(k2, wa.x, acc[li][0]);
                    acc[li][1] = ffma2(k2, wa.y, acc[li][1]);
                    acc[li][2] = ffma2(k2, wb.x, acc[li][2]);
                    acc[li][3] = ffma2(k2, wb.y, acc[li][3]);
                }
            }
        }
        // prelu(a2), dot with W3 chunk -> per-li partial scores
        float w3c[8];
        #pragma unroll
        for (int j = 0; j < 8; j++) w3c[j] = sm[F_W3 + c0 + j];
        float ps[4];
        #pragma unroll
        for (int li = 0; li < 4; li++) {
            float s = 0.f;
            #pragma unroll
            for (int j = 0; j < 4; j++) {
                float lo, hi; upk2(acc[li][j], lo, hi);
                lo = (lo >= 0.f) ? lo : pa2 * lo;
                hi = (hi >= 0.f) ? hi : pa2 * hi;
                s += lo * w3c[2 * j] + hi * w3c[2 * j + 1];
            }
            ps[li] = s;
        }
        s0 = ps[0]; s1 = ps[1]; s2 = ps[2]; s3 = ps[3];
    }
    // reduce over cg lanes (bits 0-2 of lane) — all threads participate
    #pragma unroll
    for (int o = 4; o > 0; o >>= 1) {
        s0 += __shfl_xor_sync(0xffffffffu, s0, o);
        s1 += __shfl_xor_sync(0xffffffffu, s1, o);
        s2 += __shfl_xor_sync(0xffffffffu, s2, o);
        s3 += __shfl_xor_sync(0xffffffffu, s3, o);
    }
    if (lg < 50 && cg == 0) {
        float sc[4] = {s0, s1, s2, s3};
        #pragma unroll
        for (int li = 0; li < 4; li++) {
            int l = l0 + li;
            sm[F_SC + l] = (l < len) ? (sc[li] + b3v) : NEGINF;
        }
    }
    if (t >= 400 && t < 456) sm[F_SC + (t - 200)] = FNEGINF;  // pad slots 200..255
    __syncthreads();

    // ---- softmax over 256 slots ----
    float v = 0.f, e = 0.f;
    if (t < 256) {
        v = sm[F_SC + t];
        float m = v;
        #pragma unroll
        for (int o = 16; o > 0; o >>= 1) m = fmaxf(m, __shfl_xor_sync(0xffffffffu, m, o));
        if (lane == 0) sm[F_RED + w] = m;
    }
    __syncthreads();
    if (t == 0) {
        float mm = sm[F_RED];
        for (int i = 1; i < 8; i++) mm = fmaxf(mm, sm[F_RED + i]);
        sm[F_RED + 8] = mm;
    }
    __syncthreads();
    if (t < 256) {
        float M = sm[F_RED + 8];
        e = (t < LL) ? __expf(v - M) : 0.f;
        float ss = e;
        #pragma unroll
        for (int o = 16; o > 0; o >>= 1) ss += __shfl_xor_sync(0xffffffffu, ss, o);
        if (lane == 0) sm[F_RED + 16 + w] = ss;
    }
    __syncthreads();
    if (t == 0) {
        float s = 0.f;
        for (int i = 0; i < 8; i++) s += sm[F_RED + 16 + i];
        sm[F_RED + 24] = s;
    }
    __syncthreads();
    if (t < LL) {
        float at = e / sm[F_RED + 24];
        sm[F_SC + t] = at;
        attp[(size_t)b * LL + t] = at;
    }
    __syncthreads();

    // ---- out[b][d] = sum_l att[l]*K[l][d], 4-way l split, coalesced ----
    {
        int d = t & 127, seg = t >> 7;
        float a0 = 0.f, a1 = 0.f;
        const float* Kp = sm + F_KS + d;
        const float* Ap = sm + F_SC + seg * 50;
        #pragma unroll 5
        for (int l = 0; l < 50; l += 2) {
            a0 += Ap[l]     * Kp[(seg * 50 + l) * DD];
            a1 += Ap[l + 1] * Kp[(seg * 50 + l + 1) * DD];
        }
        sm[F_OUT + seg * 128 + d] = a0 + a1;
    }
    __syncthreads();
    if (t < DD) {
        outp[(size_t)b * DD + t] = (sm[F_OUT + t] + sm[F_OUT + 128 + t])
                                 + (sm[F_OUT + 256 + t] + sm[F_OUT + 384 + t]);
    }
}

extern "C" void kernel_launch(void* const* d_in, const int* in_sizes, int n_in,
                              void* d_out, int out_size) {
    const float* query = (const float*)d_in[0];
    const float* keys  = (const float*)d_in[1];
    const int*   klen  = (const int*)  d_in[2];
    const float* W1    = (const float*)d_in[3];
    const float* b1    = (const float*)d_in[4];
    const float* a1    = (const float*)d_in[5];
    const float* W2    = (const float*)d_in[6];
    const float* b2    = (const float*)d_in[7];
    const float* a2    = (const float*)d_in[8];
    const float* W3    = (const float*)d_in[9];
    const float* b3    = (const float*)d_in[10];

    int Bn = in_sizes[0] / DD;  // 2048
    float* outp = (float*)d_out;
    float* attp = outp + (size_t)Bn * DD;

    cudaFuncSetAttribute(din_attention_rt,
                         cudaFuncAttributeMaxDynamicSharedMemorySize, SMEM_BYTES);
    din_attention_rt<<<Bn, 512, SMEM_BYTES>>>(
        query, keys, klen, W1, b1, a1, W2, b2, a2, W3, b3, outp, attp);
}

// round 10
// speedup vs baseline: 1.4060x; 1.2285x over previous
#include <cuda_runtime.h>
#include <cstdint>

// Fixed shapes: B=2048, L=200, D=128, A=64
#define DD 128
#define AA 64
#define LL 200
#define NEGINF (-4294967295.0f)
#define FNEGINF __int_as_float(0xff800000)

typedef unsigned long long ull;

__device__ __forceinline__ ull pk2(float lo, float hi) {
    ull r; asm("mov.b64 %0,{%1,%2};" : "=l"(r) : "f"(lo), "f"(hi)); return r;
}
__device__ __forceinline__ void upk2(ull v, float& lo, float& hi) {
    asm("mov.b64 {%0,%1},%2;" : "=f"(lo), "=f"(hi) : "l"(v));
}
__device__ __forceinline__ ull ffma2(ull a, ull b, ull c) {
    ull d; asm("fma.rn.f32x2 %0,%1,%2,%3;" : "=l"(d) : "l"(a), "l"(b), "l"(c)); return d;
}

// ---- smem layout (float offsets) ----
#define F_KS   0          // K [200][128], granule-XOR swizzled      25600
#define F_WC   25600      // Wc [128][64], natural                    8192
#define F_W2   33792      // W2 [64][64],  natural                    4096
#define F_H1T  37888      // h1t [64][224], granule-XOR              14336
#define F_QS   52224      // q[128]
#define F_QC   52352      // qc[64]   (16B aligned)
#define F_B2   52416      // b2[64]
#define F_W3   52480      // W3[64]
#define F_QCP  52544      // qc partials [8][64]
#define F_SC   53056      // scores/att [256]
#define F_RED  53312      // softmax scratch [32]
#define F_OUT  53344      // out partials [4][128]
#define SMEM_FLOATS 53856
#define SMEM_BYTES  (SMEM_FLOATS * 4)   // 215424 B -> 1 CTA/SM

extern "C" __global__ void __launch_bounds__(512)
din_attention_sw(const float* __restrict__ query,
                 const float* __restrict__ keys,
                 const int*   __restrict__ klen,
                 const float* __restrict__ W1,
                 const float* __restrict__ b1,
                 const float* __restrict__ a1p,
                 const float* __restrict__ W2,
                 const float* __restrict__ b2,
                 const float* __restrict__ a2p,
                 const float* __restrict__ W3,
                 const float* __restrict__ b3p,
                 float* __restrict__ outp,
                 float* __restrict__ attp)
{
    extern __shared__ float sm[];
    float4* S4 = (float4*)sm;
    const int t    = threadIdx.x;
    const int b    = blockIdx.x;
    const int lg   = t >> 3;        // 0..63 ; active if < 50
    const int cg   = t & 7;         // 0..7
    const int l0   = lg * 4;
    const int lane = t & 31;
    const int w    = t >> 5;
    // thread's column sets: cA = 4cg..4cg+3 (granule cg), cB = 32+4cg..+3 (granule 8+cg)
    const int cA = 4 * cg;
    const int cB = 32 + 4 * cg;

    const float pa1 = a1p[0], pa2 = a2p[0], b3v = b3p[0];
    const int   len = klen[b];

    // ---- Setup 1: q, W3, b2 ----
    if (t < DD) sm[F_QS + t] = query[b * DD + t];
    else if (t < DD + AA) sm[F_W3 + (t - DD)] = W3[t - DD];
    else if (t < DD + 2 * AA) sm[F_B2 + (t - DD - AA)] = b2[t - DD - AA];
    __syncthreads();

    // ---- Setup 2: Wc, W2 (natural), K copy (XOR layout), qc ----
    for (int i = t; i < DD * AA; i += 512) {
        int d = i >> 6, c = i & 63;
        sm[F_WC + i] = W1[(DD + d) * AA + c] - W1[(2 * DD + d) * AA + c]
                     + sm[F_QS + d] * W1[(3 * DD + d) * AA + c];
    }
    for (int i = t; i < AA * AA; i += 512) sm[F_W2 + i] = W2[i];
    {   // K copy, float4, granule-XOR by (row>>2)&3
        const float4* K4 = (const float4*)(keys + (size_t)b * LL * DD);
        for (int i = t; i < LL * DD / 4; i += 512) {
            int row = i >> 5, q4 = i & 31;
            S4[row * 32 + (q4 ^ ((row >> 2) & 3))] = K4[i];
        }
    }
    {   // qc[a] = b1[a] + sum_d q[d]*(W1a+W1c)[d][a]
        int a = t & 63, seg = t >> 6;
        float s = 0.f;
        #pragma unroll
        for (int d = seg * 16; d < seg * 16 + 16; d++)
            s += sm[F_QS + d] * (W1[d * AA + a] + W1[(2 * DD + d) * AA + a]);
        sm[F_QCP + seg * 64 + a] = s;
    }
    __syncthreads();
    if (t < AA) {
        float s = b1[t];
        #pragma unroll
        for (int g = 0; g < 8; g++) s += sm[F_QCP + g * 64 + t];
        sm[F_QC + t] = s;
    }
    __syncthreads();

    // ==== GEMM1: h1[l][c] = prelu(qc[c] + sum_d K[l][d]*Wc[d][c]), 4l x 8c ====
    if (lg < 50) {
        // acc[li][0..1] -> columns cA..cA+3 ; acc[li][2..3] -> cB..cB+3
        ull acc[4][4];
        {
            const ull* qa = (const ull*)(sm + F_QC + cA);
            const ull* qb = (const ull*)(sm + F_QC + cB);
            ull q0 = qa[0], q1 = qa[1], q2 = qb[0], q3 = qb[1];
            #pragma unroll
            for (int li = 0; li < 4; li++) {
                acc[li][0] = q0; acc[li][1] = q1; acc[li][2] = q2; acc[li][3] = q3;
            }
        }
        const int lp = lg & 3;           // K row-XOR key for rows l0..l0+3
        float4 kv[4], kvn[4];
        #pragma unroll
        for (int li = 0; li < 4; li++) kv[li] = S4[(l0 + li) * 32 + lp];

        #pragma unroll 1
        for (int d4 = 0; d4 < 32; d4 += 2) {
            // -- sub-iter A: prefetch d4+1, compute d4 --
            #pragma unroll
            for (int li = 0; li < 4; li++)
                kvn[li] = S4[(l0 + li) * 32 + ((d4 + 1) ^ lp)];
            #pragma unroll
            for (int dd = 0; dd < 4; dd++) {
                const float* wrow = sm + F_WC + (d4 * 4 + dd) * 64;
                ulonglong2 wa = *(const ulonglong2*)(wrow + cA);
                ulonglong2 wb = *(const ulonglong2*)(wrow + cB);
                #pragma unroll
                for (int li = 0; li < 4; li++) {
                    float kd = (dd == 0) ? kv[li].x : (dd == 1) ? kv[li].y
                             : (dd == 2) ? kv[li].z : kv[li].w;
                    ull k2 = pk2(kd, kd);
                    acc[li][0] = ffma2(k2, wa.x, acc[li][0]);
                    acc[li][1] = ffma2(k2, wa.y, acc[li][1]);
                    acc[li][2] = ffma2(k2, wb.x, acc[li][2]);
                    acc[li][3] = ffma2(k2, wb.y, acc[li][3]);
                }
            }
            // -- sub-iter B: prefetch d4+2, compute d4+1 --
            #pragma unroll
            for (int li = 0; li < 4; li++)
                kv[li] = S4[(l0 + li) * 32 + (((d4 + 2) & 31) ^ lp)];
            #pragma unroll
            for (int dd = 0; dd < 4; dd++) {
                const float* wrow = sm + F_WC + ((d4 + 1) * 4 + dd) * 64;
                ulonglong2 wa = *(const ulonglong2*)(wrow + cA);
                ulonglong2 wb = *(const ulonglong2*)(wrow + cB);
                #pragma unroll
                for (int li = 0; li < 4; li++) {
                    float kd = (dd == 0) ? kvn[li].x : (dd == 1) ? kvn[li].y
                             : (dd == 2) ? kvn[li].z : kvn[li].w;
                    ull k2 = pk2(kd, kd);
                    acc[li][0] = ffma2(k2, wa.x, acc[li][0]);
                    acc[li][1] = ffma2(k2, wa.y, acc[li][1]);
                    acc[li][2] = ffma2(k2, wb.x, acc[li][2]);
                    acc[li][3] = ffma2(k2, wb.y, acc[li][3]);
                }
            }
        }
        // prelu(a1) -> h1t rows cA..cA+3 and cB..cB+3, XOR-swizzled granule
        float hvA[4][4], hvB[4][4];   // [li][j] = column (cA|cB)+j
        #pragma unroll
        for (int li = 0; li < 4; li++) {
            float lo, hi;
            upk2(acc[li][0], lo, hi);
            hvA[li][0] = (lo >= 0.f) ? lo : pa1 * lo;
            hvA[li][1] = (hi >= 0.f) ? hi : pa1 * hi;
            upk2(acc[li][1], lo, hi);
            hvA[li][2] = (lo >= 0.f) ? lo : pa1 * lo;
            hvA[li][3] = (hi >= 0.f) ? hi : pa1 * hi;
            upk2(acc[li][2], lo, hi);
            hvB[li][0] = (lo >= 0.f) ? lo : pa1 * lo;
            hvB[li][1] = (hi >= 0.f) ? hi : pa1 * hi;
            upk2(acc[li][3], lo, hi);
            hvB[li][2] = (lo >= 0.f) ? lo : pa1 * lo;
            hvB[li][3] = (hi >= 0.f) ? hi : pa1 * hi;
        }
        #pragma unroll
        for (int j = 0; j < 4; j++) {
            int c = cA + j;
            S4[(F_H1T >> 2) + c * 56 + (lg ^ ((c >> 2) & 7))] =
                make_float4(hvA[0][j], hvA[1][j], hvA[2][j], hvA[3][j]);
        }
        #pragma unroll
        for (int j = 0; j < 4; j++) {
            int c = cB + j;
            S4[(F_H1T >> 2) + c * 56 + (lg ^ ((c >> 2) & 7))] =
                make_float4(hvB[0][j], hvB[1][j], hvB[2][j], hvB[3][j]);
        }
    }
    __syncthreads();

    // ==== GEMM2: h2[l][c] = b2[c] + sum_a h1[l][a]*W2[a][c], 4l x 8c ====
    float s0 = 0.f, s1 = 0.f, s2 = 0.f, s3 = 0.f;
    if (lg < 50) {
        ull acc[4][4];
        {
            const ull* ba = (const ull*)(sm + F_B2 + cA);
            const ull* bb = (const ull*)(sm + F_B2 + cB);
            ull q0 = ba[0], q1 = ba[1], q2 = bb[0], q3 = bb[1];
            #pragma unroll
            for (int li = 0; li < 4; li++) {
                acc[li][0] = q0; acc[li][1] = q1; acc[li][2] = q2; acc[li][3] = q3;
            }
        }
        // hq[aa] = h1t[a4*4+aa][l0..l0+3]
        float4 hq[4], hqn[4];
        #pragma unroll
        for (int aa = 0; aa < 4; aa++)
            hq[aa] = S4[(F_H1T >> 2) + aa * 56 + (lg ^ ((aa >> 2) & 7))];

        #pragma unroll 1
        for (int a4 = 0; a4 < 16; a4 += 2) {
            #pragma unroll
            for (int aa = 0; aa < 4; aa++) {
                int a = (a4 + 1) * 4 + aa;
                hqn[aa] = S4[(F_H1T >> 2) + a * 56 + (lg ^ ((a >> 2) & 7))];
            }
            #pragma unroll
            for (int aa = 0; aa < 4; aa++) {
                const float* wrow = sm + F_W2 + (a4 * 4 + aa) * 64;
                ulonglong2 wa = *(const ulonglong2*)(wrow + cA);
                ulonglong2 wb = *(const ulonglong2*)(wrow + cB);
                float4 h4 = hq[aa];
                #pragma unroll
                for (int li = 0; li < 4; li++) {
                    float hd = (li == 0) ? h4.x : (li == 1) ? h4.y
                             : (li == 2) ? h4.z : h4.w;
                    ull k2 = pk2(hd, hd);
                    acc[li][0] = ffma2(k2, wa.x, acc[li][0]);
                    acc[li][1] = ffma2(k2, wa.y, acc[li][1]);
                    acc[li][2] = ffma2(k2, wb.x, acc[li][2]);
                    acc[li][3] = ffma2(k2, wb.y, acc[li][3]);
                }
            }
            #pragma unroll
            for (int aa = 0; aa < 4; aa++) {
                int a = ((a4 + 2) & 15) * 4 + aa;
                hq[aa] = S4[(F_H1T >> 2) + a * 56 + (lg ^ ((a >> 2) & 7))];
            }
            #pragma unroll
            for (int aa = 0; aa < 4; aa++) {
                const float* wrow = sm + F_W2 + ((a4 + 1) * 4 + aa) * 64;
                ulonglong2 wa = *(const ulonglong2*)(wrow + cA);
                ulonglong2 wb = *(const ulonglong2*)(wrow + cB);
                float4 h4 = hqn[aa];
                #pragma unroll
                for (int li = 0; li < 4; li++) {
                    float hd = (li == 0) ? h4.x : (li == 1) ? h4.y
                             : (li == 2) ? h4.z : h4.w;
                    ull k2 = pk2(hd, hd);
                    acc[li][0] = ffma2(k2, wa.x, acc[li][0]);
                    acc[li][1] = ffma2(k2, wa.y, acc[li][1]);
                    acc[li][2] = ffma2(k2, wb.x, acc[li][2]);
                    acc[li][3] = ffma2(k2, wb.y, acc[li][3]);
                }
            }
        }
        // prelu(a2), dot with this thread's W3 columns
        float w3a[4], w3b[4];
        #pragma unroll
        for (int j = 0; j < 4; j++) { w3a[j] = sm[F_W3 + cA + j]; w3b[j] = sm[F_W3 + cB + j]; }
        float ps[4];
        #pragma unroll
        for (int li = 0; li < 4; li++) {
            float s = 0.f, lo, hi;
            upk2(acc[li][0], lo, hi);
            lo = (lo >= 0.f) ? lo : pa2 * lo;  hi = (hi >= 0.f) ? hi : pa2 * hi;
            s += lo * w3a[0] + hi * w3a[1];
            upk2(acc[li][1], lo, hi);
            lo = (lo >= 0.f) ? lo : pa2 * lo;  hi = (hi >= 0.f) ? hi : pa2 * hi;
            s += lo * w3a[2] + hi * w3a[3];
            upk2(acc[li][2], lo, hi);
            lo = (lo >= 0.f) ? lo : pa2 * lo;  hi = (hi >= 0.f) ? hi : pa2 * hi;
            s += lo * w3b[0] + hi * w3b[1];
            upk2(acc[li][3], lo, hi);
            lo = (lo >= 0.f) ? lo : pa2 * lo;  hi = (hi >= 0.f) ? hi : pa2 * hi;
            s += lo * w3b[2] + hi * w3b[3];
            ps[li] = s;
        }
        s0 = ps[0]; s1 = ps[1]; s2 = ps[2]; s3 = ps[3];
    }
    #pragma unroll
    for (int o = 4; o > 0; o >>= 1) {
        s0 += __shfl_xor_sync(0xffffffffu, s0, o);
        s1 += __shfl_xor_sync(0xffffffffu, s1, o);
        s2 += __shfl_xor_sync(0xffffffffu, s2, o);
        s3 += __shfl_xor_sync(0xffffffffu, s3, o);
    }
    if (lg < 50 && cg == 0) {
        float sc[4] = {s0, s1, s2, s3};
        #pragma unroll
        for (int li = 0; li < 4; li++) {
            int l = l0 + li;
            sm[F_SC + l] = (l < len) ? (sc[li] + b3v) : NEGINF;
        }
    }
    if (t >= 400 && t < 456) sm[F_SC + (t - 200)] = FNEGINF;
    __syncthreads();

    // ---- softmax over 256 slots ----
    float v = 0.f, e = 0.f;
    if (t < 256) {
        v = sm[F_SC + t];
        float m = v;
        #pragma unroll
        for (int o = 16; o > 0; o >>= 1) m = fmaxf(m, __shfl_xor_sync(0xffffffffu, m, o));
        if (lane == 0) sm[F_RED + w] = m;
    }
    __syncthreads();
    if (t == 0) {
        float mm = sm[F_RED];
        for (int i = 1; i < 8; i++) mm = fmaxf(mm, sm[F_RED + i]);
        sm[F_RED + 8] = mm;
    }
    __syncthreads();
    if (t < 256) {
        float M = sm[F_RED + 8];
        e = (t < LL) ? __expf(v - M) : 0.f;
        float ss = e;
        #pragma unroll
        for (int o = 16; o > 0; o >>= 1) ss += __shfl_xor_sync(0xffffffffu, ss, o);
        if (lane == 0) sm[F_RED + 16 + w] = ss;
    }
    __syncthreads();
    if (t == 0) {
        float s = 0.f;
        for (int i = 0; i < 8; i++) s += sm[F_RED + 16 + i];
        sm[F_RED + 24] = s;
    }
    __syncthreads();
    if (t < LL) {
        float at = e / sm[F_RED + 24];
        sm[F_SC + t] = at;
        attp[(size_t)b * LL + t] = at;
    }
    __syncthreads();

    // ---- out[b][d] = sum_l att[l]*K[l][d], 4-way l split (swizzled K read) ----
    {
        int d = t & 127, seg = t >> 7;
        int q4 = d >> 2, dc = d & 3;
        float a0 = 0.f, a1 = 0.f;
        const float* Ap = sm + F_SC + seg * 50;
        #pragma unroll 5
        for (int l2 = 0; l2 < 50; l2 += 2) {
            int la = seg * 50 + l2, lb = la + 1;
            float ka = sm[la * 128 + (q4 ^ ((la >> 2) & 3)) * 4 + dc];
            float kb = sm[lb * 128 + (q4 ^ ((lb >> 2) & 3)) * 4 + dc];
            a0 += Ap[l2] * ka;
            a1 += Ap[l2 + 1] * kb;
        }
        sm[F_OUT + seg * 128 + d] = a0 + a1;
    }
    __syncthreads();
    if (t < DD) {
        outp[(size_t)b * DD + t] = (sm[F_OUT + t] + sm[F_OUT + 128 + t])
                                 + (sm[F_OUT + 256 + t] + sm[F_OUT + 384 + t]);
    }
}

extern "C" void kernel_launch(void* const* d_in, const int* in_sizes, int n_in,
                              void* d_out, int out_size) {
    const float* query = (const float*)d_in[0];
    const float* keys  = (const float*)d_in[1];
    const int*   klen  = (const int*)  d_in[2];
    const float* W1    = (const float*)d_in[3];
    const float* b1    = (const float*)d_in[4];
    const float* a1    = (const float*)d_in[5];
    const float* W2    = (const float*)d_in[6];
    const float* b2    = (const float*)d_in[7];
    const float* a2    = (const float*)d_in[8];
    const float* W3    = (const float*)d_in[9];
    const float* b3    = (const float*)d_in[10];

    int Bn = in_sizes[0] / DD;  // 2048
    float* outp = (float*)d_out;
    float* attp = outp + (size_t)Bn * DD;

    cudaFuncSetAttribute(din_attention_sw,
                         cudaFuncAttributeMaxDynamicSharedMemorySize, SMEM_BYTES);
    din_attention_sw<<<Bn, 512, SMEM_BYTES>>>(
        query, keys, klen, W1, b1, a1, W2, b2, a2, W3, b3, outp, attp);
}